// round 1
// baseline (speedup 1.0000x reference)
#include <cuda_runtime.h>
#include <cstdint>

#define HF 128
#define LSEQ 2048
#define BATCH 128
#define CHUNK 256
#define ELEMS 4

// ---------- packed f32x2 helpers (Blackwell 2x fp32) ----------
__device__ __forceinline__ unsigned long long pk2(float lo, float hi) {
    unsigned long long r;
    asm("mov.b64 %0, {%1, %2};" : "=l"(r) : "f"(lo), "f"(hi));
    return r;
}
__device__ __forceinline__ unsigned long long ffma2(unsigned long long a,
                                                    unsigned long long b,
                                                    unsigned long long c) {
    unsigned long long d;
    asm("fma.rn.f32x2 %0, %1, %2, %3;" : "=l"(d) : "l"(a), "l"(b), "l"(c));
    return d;
}
__device__ __forceinline__ float2 unpk2(unsigned long long a) {
    float x, y;
    asm("mov.b64 {%0, %1}, %2;" : "=f"(x), "=f"(y) : "l"(a));
    return make_float2(x, y);
}

__global__ void zero_out_kernel(float* out) { out[threadIdx.x] = 0.f; }

// TYPE 0: bond length MLP  (G=1 geo scalar, NE=2 embeddings, D=33)
// TYPE 1: angle MLP        (G=1, NE=3, D=49)
// TYPE 2: dihedral MLP     (G=2, NE=4, D=66)
template <int TYPE, int D, int G, int NE>
__global__ __launch_bounds__(128, 2)
void mlp_energy_kernel(const float* __restrict__ R, const int* __restrict__ seq,
                       const float* __restrict__ emb,
                       const float* __restrict__ W1, const float* __restrict__ b1,
                       const float* __restrict__ W2, const float* __restrict__ b2,
                       const float* __restrict__ W3, const float* __restrict__ b3,
                       float* __restrict__ out) {
    constexpr int N   = LSEQ - 1 - TYPE;     // elements per batch
    constexpr int Dp  = (D + 3) & ~3;        // pad feature dim to x4
    constexpr int Dp4 = Dp / 4;

    __shared__ float4 s_w1[Dp4 * HF];        // W1 padded, row-group-of-4 major
    __shared__ float  s_emb[20 * 16];
    __shared__ int    s_seq[CHUNK + 4];
    __shared__ float  s_geo[CHUNK * G];
    __shared__ float4 s_x4[ELEMS * Dp4];
    __shared__ float4 s_h14[ELEMS * (HF / 4)];
    __shared__ float  s_red[4 * ELEMS];

    float* s_x  = (float*)s_x4;
    float* s_h1 = (float*)s_h14;

    const int tid    = threadIdx.x;
    const int j      = tid;          // output column owned by this thread
    const int lane   = tid & 31;
    const int warp   = tid >> 5;
    const int b      = blockIdx.y;
    const int cstart = blockIdx.x * CHUNK;

    // ---- embedding table to smem ----
    for (int t = tid; t < 20 * 16; t += 128) s_emb[t] = emb[t];
    // ---- seq slice (with slack for +k lookahead) ----
    for (int t = tid; t < CHUNK + 4; t += 128) {
        int idx = cstart + t;
        if (idx >= LSEQ) idx = LSEQ - 1;
        s_seq[t] = seq[b * LSEQ + idx];
    }
    // ---- per-column scalars ----
    const float b1j = b1[j];
    const float b2j = b2[j];
    const float w3j = W3[j];
    const float b3s = b3[0];
    // ---- W1 -> smem (zero-padded rows) ----
    #pragma unroll
    for (int i4 = 0; i4 < Dp4; i4++) {
        float4 q;
        q.x = (4 * i4 + 0 < D) ? W1[(4 * i4 + 0) * HF + j] : 0.f;
        q.y = (4 * i4 + 1 < D) ? W1[(4 * i4 + 1) * HF + j] : 0.f;
        q.z = (4 * i4 + 2 < D) ? W1[(4 * i4 + 2) * HF + j] : 0.f;
        q.w = (4 * i4 + 3 < D) ? W1[(4 * i4 + 3) * HF + j] : 0.f;
        s_w1[i4 * HF + j] = q;
    }
    // ---- W2 column j into registers as packed pairs ----
    unsigned long long w2p[64];
    #pragma unroll
    for (int i2 = 0; i2 < 64; i2++) {
        float lo = __ldg(&W2[(2 * i2 + 0) * HF + j]);
        float hi = __ldg(&W2[(2 * i2 + 1) * HF + j]);
        w2p[i2] = pk2(lo, hi);
    }
    // ---- geometry scalars for the whole chunk (fully parallel) ----
    const float* Rb = R + (size_t)b * LSEQ * 3;
    for (int t = tid; t < CHUNK; t += 128) {
        int i = cstart + t;
        if (i < N) {
            if (TYPE == 0) {
                float dx = __ldg(&Rb[(i + 1) * 3 + 0]) - __ldg(&Rb[i * 3 + 0]);
                float dy = __ldg(&Rb[(i + 1) * 3 + 1]) - __ldg(&Rb[i * 3 + 1]);
                float dz = __ldg(&Rb[(i + 1) * 3 + 2]) - __ldg(&Rb[i * 3 + 2]);
                s_geo[t] = sqrtf(dx * dx + dy * dy + dz * dz);
            } else if (TYPE == 1) {
                float ax = __ldg(&Rb[i * 3 + 0]), ay = __ldg(&Rb[i * 3 + 1]), az = __ldg(&Rb[i * 3 + 2]);
                float bx = __ldg(&Rb[(i + 1) * 3 + 0]), by = __ldg(&Rb[(i + 1) * 3 + 1]), bz = __ldg(&Rb[(i + 1) * 3 + 2]);
                float cx = __ldg(&Rb[(i + 2) * 3 + 0]), cy = __ldg(&Rb[(i + 2) * 3 + 1]), cz = __ldg(&Rb[(i + 2) * 3 + 2]);
                float ux = ax - bx, uy = ay - by, uz = az - bz;  // -d[i]
                float vx = cx - bx, vy = cy - by, vz = cz - bz;  //  d[i+1]
                float num = ux * vx + uy * vy + uz * vz;
                float den = sqrtf((ux * ux + uy * uy + uz * uz) * (vx * vx + vy * vy + vz * vz));
                float c = num / den;
                s_geo[t] = fminf(1.f, fmaxf(-1.f, c));
            } else {
                float p0x = __ldg(&Rb[i * 3 + 0]), p0y = __ldg(&Rb[i * 3 + 1]), p0z = __ldg(&Rb[i * 3 + 2]);
                float p1x = __ldg(&Rb[(i + 1) * 3 + 0]), p1y = __ldg(&Rb[(i + 1) * 3 + 1]), p1z = __ldg(&Rb[(i + 1) * 3 + 2]);
                float p2x = __ldg(&Rb[(i + 2) * 3 + 0]), p2y = __ldg(&Rb[(i + 2) * 3 + 1]), p2z = __ldg(&Rb[(i + 2) * 3 + 2]);
                float p3x = __ldg(&Rb[(i + 3) * 3 + 0]), p3y = __ldg(&Rb[(i + 3) * 3 + 1]), p3z = __ldg(&Rb[(i + 3) * 3 + 2]);
                float b1x = p1x - p0x, b1y = p1y - p0y, b1z = p1z - p0z;
                float b2x = p2x - p1x, b2y = p2y - p1y, b2z = p2z - p1z;
                float b3x = p3x - p2x, b3y = p3y - p2y, b3z = p3z - p2z;
                // n1 = b1 x b2 ; n2 = b2 x b3
                float n1x = b1y * b2z - b1z * b2y, n1y = b1z * b2x - b1x * b2z, n1z = b1x * b2y - b1y * b2x;
                float n2x = b2y * b3z - b2z * b3y, n2y = b2z * b3x - b2x * b3z, n2z = b2x * b3y - b2y * b3x;
                float inv = rsqrtf(b2x * b2x + b2y * b2y + b2z * b2z);
                float ux = b2x * inv, uy = b2y * inv, uz = b2z * inv;
                // m1 = n1 x b2u
                float m1x = n1y * uz - n1z * uy, m1y = n1z * ux - n1x * uz, m1z = n1x * uy - n1y * ux;
                float yv = m1x * n2x + m1y * n2y + m1z * n2z;  // sin numerator
                float xv = n1x * n2x + n1y * n2y + n1z * n2z;  // cos numerator
                float rn = rsqrtf(xv * xv + yv * yv);          // sin/cos of atan2(y,x)
                s_geo[t * 2 + 0] = yv * rn;
                s_geo[t * 2 + 1] = xv * rn;
            }
        } else {
            if (G == 1) s_geo[t] = 0.f;
            else { s_geo[t * 2 + 0] = 0.f; s_geo[t * 2 + 1] = 0.f; }
        }
    }
    __syncthreads();

    float block_sum = 0.f;

    for (int g0 = 0; g0 < CHUNK; g0 += ELEMS) {
        // ---- cooperative feature assembly: x[e][0:Dp] ----
        for (int t = tid; t < ELEMS * Dp; t += 128) {
            int e = t / Dp;
            int v = t - e * Dp;
            int li = g0 + e;
            int gi = cstart + li;
            float val = 0.f;
            if (gi < N && v < D) {
                if (v < G) {
                    val = s_geo[li * G + v];
                } else {
                    int k = (v - G) >> 4;
                    int c = (v - G) & 15;
                    val = s_emb[s_seq[li + k] * 16 + c];
                }
            }
            s_x[t] = val;
        }
        __syncthreads();

        // ---- layer 1: h1[e][j] = relu(b1[j] + x . W1[:,j]) ----
        unsigned long long a1[ELEMS];
        #pragma unroll
        for (int e = 0; e < ELEMS; e++) a1[e] = pk2(b1j, 0.f);
        #pragma unroll
        for (int i4 = 0; i4 < Dp4; i4++) {
            float4 w = s_w1[i4 * HF + j];
            unsigned long long w0 = pk2(w.x, w.y);
            unsigned long long w1q = pk2(w.z, w.w);
            #pragma unroll
            for (int e = 0; e < ELEMS; e++) {
                float4 xq = s_x4[e * Dp4 + i4];
                a1[e] = ffma2(pk2(xq.x, xq.y), w0, a1[e]);
                a1[e] = ffma2(pk2(xq.z, xq.w), w1q, a1[e]);
            }
        }
        #pragma unroll
        for (int e = 0; e < ELEMS; e++) {
            float2 u = unpk2(a1[e]);
            s_h1[e * HF + j] = fmaxf(u.x + u.y, 0.f);
        }
        __syncthreads();

        // ---- layer 2: h2[e][j] = relu(b2[j] + h1 . W2[:,j]) (W2 col in regs) ----
        unsigned long long a2[ELEMS];
        #pragma unroll
        for (int e = 0; e < ELEMS; e++) a2[e] = pk2(b2j, 0.f);
        #pragma unroll
        for (int i4 = 0; i4 < 32; i4++) {
            #pragma unroll
            for (int e = 0; e < ELEMS; e++) {
                float4 hq = s_h14[e * 32 + i4];
                a2[e] = ffma2(pk2(hq.x, hq.y), w2p[2 * i4 + 0], a2[e]);
                a2[e] = ffma2(pk2(hq.z, hq.w), w2p[2 * i4 + 1], a2[e]);
            }
        }
        // ---- layer 3 partial + block reduce ----
        float p[ELEMS];
        #pragma unroll
        for (int e = 0; e < ELEMS; e++) {
            float2 u = unpk2(a2[e]);
            p[e] = fmaxf(u.x + u.y, 0.f) * w3j;
        }
        #pragma unroll
        for (int e = 0; e < ELEMS; e++) {
            #pragma unroll
            for (int off = 16; off; off >>= 1)
                p[e] += __shfl_xor_sync(0xffffffffu, p[e], off);
        }
        if (lane == 0) {
            #pragma unroll
            for (int e = 0; e < ELEMS; e++) s_red[warp * ELEMS + e] = p[e];
        }
        __syncthreads();
        if (tid == 0) {
            #pragma unroll
            for (int e = 0; e < ELEMS; e++) {
                if (cstart + g0 + e < N) {
                    block_sum += s_red[0 * ELEMS + e] + s_red[1 * ELEMS + e] +
                                 s_red[2 * ELEMS + e] + s_red[3 * ELEMS + e] + b3s;
                }
            }
        }
        // safe: next group's s_red writes are fenced behind two more barriers
    }

    if (tid == 0) atomicAdd(&out[b], block_sum);
}

extern "C" void kernel_launch(void* const* d_in, const int* in_sizes, int n_in,
                              void* d_out, int out_size) {
    const float* R   = (const float*)d_in[0];
    const int*   seq = (const int*)d_in[1];
    const float* emb = (const float*)d_in[2];
    const float* fl_W1 = (const float*)d_in[3];
    const float* fl_b1 = (const float*)d_in[4];
    const float* fl_W2 = (const float*)d_in[5];
    const float* fl_b2 = (const float*)d_in[6];
    const float* fl_W3 = (const float*)d_in[7];
    const float* fl_b3 = (const float*)d_in[8];
    const float* ft_W1 = (const float*)d_in[9];
    const float* ft_b1 = (const float*)d_in[10];
    const float* ft_W2 = (const float*)d_in[11];
    const float* ft_b2 = (const float*)d_in[12];
    const float* ft_W3 = (const float*)d_in[13];
    const float* ft_b3 = (const float*)d_in[14];
    const float* fp_W1 = (const float*)d_in[15];
    const float* fp_b1 = (const float*)d_in[16];
    const float* fp_W2 = (const float*)d_in[17];
    const float* fp_b2 = (const float*)d_in[18];
    const float* fp_W3 = (const float*)d_in[19];
    const float* fp_b3 = (const float*)d_in[20];
    float* out = (float*)d_out;

    zero_out_kernel<<<1, 128>>>(out);

    dim3 grid((LSEQ + CHUNK - 1) / CHUNK, BATCH);  // 8 x 128
    mlp_energy_kernel<0, 33, 1, 2><<<grid, 128>>>(R, seq, emb, fl_W1, fl_b1, fl_W2, fl_b2, fl_W3, fl_b3, out);
    mlp_energy_kernel<1, 49, 1, 3><<<grid, 128>>>(R, seq, emb, ft_W1, ft_b1, ft_W2, ft_b2, ft_W3, ft_b3, out);
    mlp_energy_kernel<2, 66, 2, 4><<<grid, 128>>>(R, seq, emb, fp_W1, fp_b1, fp_W2, fp_b2, fp_W3, fp_b3, out);
}

// round 2
// speedup vs baseline: 1.4499x; 1.4499x over previous
#include <cuda_runtime.h>
#include <cstdint>

#define HF 128
#define LSEQ 2048
#define BATCH 128
#define CHUNK 512
#define ELEMS 8

// ---------- packed f32x2 helpers (Blackwell 2x fp32) ----------
__device__ __forceinline__ unsigned long long pk2(float lo, float hi) {
    unsigned long long r;
    asm("mov.b64 %0, {%1, %2};" : "=l"(r) : "f"(lo), "f"(hi));
    return r;
}
__device__ __forceinline__ unsigned long long ffma2(unsigned long long a,
                                                    unsigned long long b,
                                                    unsigned long long c) {
    unsigned long long d;
    asm("fma.rn.f32x2 %0, %1, %2, %3;" : "=l"(d) : "l"(a), "l"(b), "l"(c));
    return d;
}
__device__ __forceinline__ float2 unpk2(unsigned long long a) {
    float x, y;
    asm("mov.b64 {%0, %1}, %2;" : "=f"(x), "=f"(y) : "l"(a));
    return make_float2(x, y);
}

__global__ void zero_out_kernel(float* out) { out[threadIdx.x] = 0.f; }

// TYPE 0: bond length MLP  (G=1 geo scalar, D=33)
// TYPE 1: angle MLP        (G=1, D=49)
// TYPE 2: dihedral MLP     (G=2, D=66)
template <int TYPE, int D, int G>
__device__ __forceinline__ void run_mlp(
        const float* __restrict__ R, const int* __restrict__ seq,
        const float* __restrict__ emb,
        const float* __restrict__ W1, const float* __restrict__ b1,
        const float* __restrict__ W2, const float* __restrict__ b2,
        const float* __restrict__ W3, const float* __restrict__ b3,
        float* __restrict__ out) {
    constexpr int N   = LSEQ - 1 - TYPE;     // elements per batch
    constexpr int Dp  = (D + 3) & ~3;        // pad feature dim to x4
    constexpr int Dp4 = Dp / 4;
    constexpr int Dp2 = Dp / 2;

    __shared__ float  s_emb[20 * 16];
    __shared__ int    s_seq[CHUNK + 4];
    __shared__ float  s_geo[CHUNK * G];
    __shared__ float4 s_x4[ELEMS * Dp4];
    __shared__ float4 s_h14[ELEMS * (HF / 4)];
    __shared__ float  s_red[4];

    float* s_x  = (float*)s_x4;
    float* s_h1 = (float*)s_h14;

    const int tid    = threadIdx.x;
    const int j      = tid;          // output column owned by this thread
    const int lane   = tid & 31;
    const int warp   = tid >> 5;
    const int b      = blockIdx.y;
    const int cstart = blockIdx.x * CHUNK;

    // ---- embedding table to smem ----
    for (int t = tid; t < 20 * 16; t += 128) s_emb[t] = emb[t];
    // ---- seq slice (with slack for +k lookahead) ----
    for (int t = tid; t < CHUNK + 4; t += 128) {
        int idx = cstart + t;
        if (idx >= LSEQ) idx = LSEQ - 1;
        s_seq[t] = seq[b * LSEQ + idx];
    }
    // ---- per-column scalars ----
    const float b1j = b1[j];
    const float b2j = b2[j];
    const float w3j = W3[j];
    const float b3s = b3[0];
    // ---- W1 column j -> registers as packed k-pairs (zero padded) ----
    unsigned long long w1p[Dp2];
    #pragma unroll
    for (int p = 0; p < Dp2; p++) {
        float lo = (2 * p + 0 < D) ? __ldg(&W1[(2 * p + 0) * HF + j]) : 0.f;
        float hi = (2 * p + 1 < D) ? __ldg(&W1[(2 * p + 1) * HF + j]) : 0.f;
        w1p[p] = pk2(lo, hi);
    }
    // ---- W2 column j -> registers as packed k-pairs ----
    unsigned long long w2p[64];
    #pragma unroll
    for (int p = 0; p < 64; p++) {
        float lo = __ldg(&W2[(2 * p + 0) * HF + j]);
        float hi = __ldg(&W2[(2 * p + 1) * HF + j]);
        w2p[p] = pk2(lo, hi);
    }
    // ---- geometry scalars for the whole chunk (fully parallel) ----
    const float* Rb = R + (size_t)b * LSEQ * 3;
    for (int t = tid; t < CHUNK; t += 128) {
        int i = cstart + t;
        if (i < N) {
            if (TYPE == 0) {
                float dx = __ldg(&Rb[(i + 1) * 3 + 0]) - __ldg(&Rb[i * 3 + 0]);
                float dy = __ldg(&Rb[(i + 1) * 3 + 1]) - __ldg(&Rb[i * 3 + 1]);
                float dz = __ldg(&Rb[(i + 1) * 3 + 2]) - __ldg(&Rb[i * 3 + 2]);
                s_geo[t] = sqrtf(dx * dx + dy * dy + dz * dz);
            } else if (TYPE == 1) {
                float ax = __ldg(&Rb[i * 3 + 0]), ay = __ldg(&Rb[i * 3 + 1]), az = __ldg(&Rb[i * 3 + 2]);
                float bx = __ldg(&Rb[(i + 1) * 3 + 0]), by = __ldg(&Rb[(i + 1) * 3 + 1]), bz = __ldg(&Rb[(i + 1) * 3 + 2]);
                float cx = __ldg(&Rb[(i + 2) * 3 + 0]), cy = __ldg(&Rb[(i + 2) * 3 + 1]), cz = __ldg(&Rb[(i + 2) * 3 + 2]);
                float ux = ax - bx, uy = ay - by, uz = az - bz;  // -d[i]
                float vx = cx - bx, vy = cy - by, vz = cz - bz;  //  d[i+1]
                float num = ux * vx + uy * vy + uz * vz;
                float den = sqrtf((ux * ux + uy * uy + uz * uz) * (vx * vx + vy * vy + vz * vz));
                float c = num / den;
                s_geo[t] = fminf(1.f, fmaxf(-1.f, c));
            } else {
                float p0x = __ldg(&Rb[i * 3 + 0]), p0y = __ldg(&Rb[i * 3 + 1]), p0z = __ldg(&Rb[i * 3 + 2]);
                float p1x = __ldg(&Rb[(i + 1) * 3 + 0]), p1y = __ldg(&Rb[(i + 1) * 3 + 1]), p1z = __ldg(&Rb[(i + 1) * 3 + 2]);
                float p2x = __ldg(&Rb[(i + 2) * 3 + 0]), p2y = __ldg(&Rb[(i + 2) * 3 + 1]), p2z = __ldg(&Rb[(i + 2) * 3 + 2]);
                float p3x = __ldg(&Rb[(i + 3) * 3 + 0]), p3y = __ldg(&Rb[(i + 3) * 3 + 1]), p3z = __ldg(&Rb[(i + 3) * 3 + 2]);
                float b1x = p1x - p0x, b1y = p1y - p0y, b1z = p1z - p0z;
                float b2x = p2x - p1x, b2y = p2y - p1y, b2z = p2z - p1z;
                float b3x = p3x - p2x, b3y = p3y - p2y, b3z = p3z - p2z;
                float n1x = b1y * b2z - b1z * b2y, n1y = b1z * b2x - b1x * b2z, n1z = b1x * b2y - b1y * b2x;
                float n2x = b2y * b3z - b2z * b3y, n2y = b2z * b3x - b2x * b3z, n2z = b2x * b3y - b2y * b3x;
                float inv = rsqrtf(b2x * b2x + b2y * b2y + b2z * b2z);
                float ux = b2x * inv, uy = b2y * inv, uz = b2z * inv;
                float m1x = n1y * uz - n1z * uy, m1y = n1z * ux - n1x * uz, m1z = n1x * uy - n1y * ux;
                float yv = m1x * n2x + m1y * n2y + m1z * n2z;  // sin numerator
                float xv = n1x * n2x + n1y * n2y + n1z * n2z;  // cos numerator
                float rn = rsqrtf(xv * xv + yv * yv);
                s_geo[t * 2 + 0] = yv * rn;
                s_geo[t * 2 + 1] = xv * rn;
            }
        } else {
            if (G == 1) s_geo[t] = 0.f;
            else { s_geo[t * 2 + 0] = 0.f; s_geo[t * 2 + 1] = 0.f; }
        }
    }
    __syncthreads();

    float thread_sum = 0.f;

    for (int g0 = 0; g0 < CHUNK; g0 += ELEMS) {
        // ---- cooperative feature assembly: x[e][0:Dp] ----
        for (int t = tid; t < ELEMS * Dp; t += 128) {
            int e = t / Dp;
            int v = t - e * Dp;
            int li = g0 + e;
            int gi = cstart + li;
            float val = 0.f;
            if (gi < N && v < D) {
                if (v < G) {
                    val = s_geo[li * G + v];
                } else {
                    int k = (v - G) >> 4;
                    int c = (v - G) & 15;
                    val = s_emb[s_seq[li + k] * 16 + c];
                }
            }
            s_x[t] = val;
        }
        __syncthreads();

        // ---- layer 1: h1[e][j] = relu(b1[j] + x . W1[:,j]) (W1 col in regs) ----
        unsigned long long a1[ELEMS];
        #pragma unroll
        for (int e = 0; e < ELEMS; e++) a1[e] = pk2(b1j, 0.f);
        #pragma unroll
        for (int i4 = 0; i4 < Dp4; i4++) {
            #pragma unroll
            for (int e = 0; e < ELEMS; e++) {
                float4 xq = s_x4[e * Dp4 + i4];
                a1[e] = ffma2(pk2(xq.x, xq.y), w1p[2 * i4 + 0], a1[e]);
                a1[e] = ffma2(pk2(xq.z, xq.w), w1p[2 * i4 + 1], a1[e]);
            }
        }
        #pragma unroll
        for (int e = 0; e < ELEMS; e++) {
            float2 u = unpk2(a1[e]);
            s_h1[e * HF + j] = fmaxf(u.x + u.y, 0.f);
        }
        __syncthreads();

        // ---- layer 2 + 3: thread_sum += relu(b2 + h1.W2[:,j]) * W3[j] ----
        unsigned long long a2[ELEMS];
        #pragma unroll
        for (int e = 0; e < ELEMS; e++) a2[e] = pk2(b2j, 0.f);
        #pragma unroll
        for (int i4 = 0; i4 < HF / 4; i4++) {
            #pragma unroll
            for (int e = 0; e < ELEMS; e++) {
                float4 hq = s_h14[e * (HF / 4) + i4];
                a2[e] = ffma2(pk2(hq.x, hq.y), w2p[2 * i4 + 0], a2[e]);
                a2[e] = ffma2(pk2(hq.z, hq.w), w2p[2 * i4 + 1], a2[e]);
            }
        }
        #pragma unroll
        for (int e = 0; e < ELEMS; e++) {
            float2 u = unpk2(a2[e]);
            float v = fmaxf(u.x + u.y, 0.f) * w3j;
            bool valid = (cstart + g0 + e) < N;
            thread_sum += valid ? v : 0.f;
        }
        // next iteration's s_x writes are safe: all reads of s_x done before
        // the h1 barrier; next h1 writes are fenced by the next x barrier.
    }

    // ---- one block reduction at the end ----
    #pragma unroll
    for (int off = 16; off; off >>= 1)
        thread_sum += __shfl_xor_sync(0xffffffffu, thread_sum, off);
    if (lane == 0) s_red[warp] = thread_sum;
    __syncthreads();
    if (tid == 0) {
        int count = N - cstart;
        if (count > CHUNK) count = CHUNK;
        float total = s_red[0] + s_red[1] + s_red[2] + s_red[3] + (float)count * b3s;
        atomicAdd(&out[b], total);
    }
}

__global__ __launch_bounds__(128, 2)
void fused_energy_kernel(const float* __restrict__ R, const int* __restrict__ seq,
                         const float* __restrict__ emb,
                         const float* fl_W1, const float* fl_b1, const float* fl_W2,
                         const float* fl_b2, const float* fl_W3, const float* fl_b3,
                         const float* ft_W1, const float* ft_b1, const float* ft_W2,
                         const float* ft_b2, const float* ft_W3, const float* ft_b3,
                         const float* fp_W1, const float* fp_b1, const float* fp_W2,
                         const float* fp_b2, const float* fp_W3, const float* fp_b3,
                         float* __restrict__ out) {
    if (blockIdx.z == 0) {
        run_mlp<0, 33, 1>(R, seq, emb, fl_W1, fl_b1, fl_W2, fl_b2, fl_W3, fl_b3, out);
    } else if (blockIdx.z == 1) {
        run_mlp<1, 49, 1>(R, seq, emb, ft_W1, ft_b1, ft_W2, ft_b2, ft_W3, ft_b3, out);
    } else {
        run_mlp<2, 66, 2>(R, seq, emb, fp_W1, fp_b1, fp_W2, fp_b2, fp_W3, fp_b3, out);
    }
}

extern "C" void kernel_launch(void* const* d_in, const int* in_sizes, int n_in,
                              void* d_out, int out_size) {
    const float* R   = (const float*)d_in[0];
    const int*   seq = (const int*)d_in[1];
    const float* emb = (const float*)d_in[2];
    const float* fl_W1 = (const float*)d_in[3];
    const float* fl_b1 = (const float*)d_in[4];
    const float* fl_W2 = (const float*)d_in[5];
    const float* fl_b2 = (const float*)d_in[6];
    const float* fl_W3 = (const float*)d_in[7];
    const float* fl_b3 = (const float*)d_in[8];
    const float* ft_W1 = (const float*)d_in[9];
    const float* ft_b1 = (const float*)d_in[10];
    const float* ft_W2 = (const float*)d_in[11];
    const float* ft_b2 = (const float*)d_in[12];
    const float* ft_W3 = (const float*)d_in[13];
    const float* ft_b3 = (const float*)d_in[14];
    const float* fp_W1 = (const float*)d_in[15];
    const float* fp_b1 = (const float*)d_in[16];
    const float* fp_W2 = (const float*)d_in[17];
    const float* fp_b2 = (const float*)d_in[18];
    const float* fp_W3 = (const float*)d_in[19];
    const float* fp_b3 = (const float*)d_in[20];
    float* out = (float*)d_out;

    zero_out_kernel<<<1, 128>>>(out);

    dim3 grid(LSEQ / CHUNK, BATCH, 3);  // 4 x 128 x 3
    fused_energy_kernel<<<grid, 128>>>(R, seq, emb,
        fl_W1, fl_b1, fl_W2, fl_b2, fl_W3, fl_b3,
        ft_W1, ft_b1, ft_W2, ft_b2, ft_W3, ft_b3,
        fp_W1, fp_b1, fp_W2, fp_b2, fp_W3, fp_b3, out);
}